// round 11
// baseline (speedup 1.0000x reference)
#include <cuda_runtime.h>
#include <cuda_fp16.h>
#include <cstdint>

// Problem constants
#define B_    256
#define T_    128
#define NIN   1156
#define NHID  1024
#define NOUT  10
#define M_    (T_ * B_)
#define BETA  0.95f
#define THR   1.0f
#define NINP  1184                 // NIN padded to 37*32 (zero-filled)
#define K4    (NINP / 4)           // 296

// Scratch
__device__ float    g_cur[(size_t)M_ * NHID];
__device__ unsigned g_spk[(size_t)M_ * NHID / 32];
__device__ float    g_y  [(size_t)M_ * NOUT];
__device__ __half   g_xhi[(size_t)M_ * NINP];
__device__ int8_t   g_xa8[(size_t)M_ * NINP];
__device__ int8_t   g_xl8[(size_t)M_ * NINP];
__device__ __half   g_whi[(size_t)NHID * NINP];
__device__ int8_t   g_w8 [(size_t)NHID * NINP];
__device__ int8_t   g_wl8[(size_t)NHID * NINP];
__device__ float    g_ch [NHID];          // C[h] = sum(wl8)*2^-25

__device__ __forceinline__ int s8cl(float v) {
    int r = __float2int_rn(v);
    return r < -128 ? -128 : (r > 127 ? 127 : r);
}
__device__ __forceinline__ uint32_t pack4(int a, int b, int c, int d) {
    return (uint32_t)(a & 255) | ((uint32_t)(b & 255) << 8) |
           ((uint32_t)(c & 255) << 16) | ((uint32_t)(d & 255) << 24);
}

// ---------------------------------------------------------------------------
// Pre-pass: X -> xhi (fp16), xa8 (rn(a*128-64)), xl8 (rn(a_lo*2^19))
// m = t*256+b, rows padded to NINP with zeros.
// ---------------------------------------------------------------------------
__global__ __launch_bounds__(256)
void split_x_kernel(const float* __restrict__ x)
{
    const int idx = blockIdx.x * blockDim.x + threadIdx.x;  // M_*K4
    const int m  = idx / K4;
    const int k4 = idx - m * K4;
    const int k  = k4 * 4;
    const int t  = m >> 8;
    const int b  = m & 255;
    float4 v = make_float4(0.f, 0.f, 0.f, 0.f);
    if (k < NIN)
        v = *reinterpret_cast<const float4*>(x + ((size_t)b * T_ + t) * NIN + k);
    float vv[4] = {v.x, v.y, v.z, v.w};
    __half h[4]; float lo[4]; int a8[4], l8[4];
#pragma unroll
    for (int i = 0; i < 4; i++) {
        h[i]  = __float2half_rn(vv[i]);
        lo[i] = vv[i] - __half2float(h[i]);
        a8[i] = s8cl(vv[i] * 128.f - 64.f);
        l8[i] = s8cl(lo[i] * 524288.f);            // 2^19
    }
    // padding rows: v=0 -> a8=-64, but W-side is 0 there, so products vanish.
    const size_t o = (size_t)m * NINP + k;
    __half2 h0 = __halves2half2(h[0], h[1]);
    __half2 h1 = __halves2half2(h[2], h[3]);
    uint2 hp = make_uint2(*reinterpret_cast<uint32_t*>(&h0),
                          *reinterpret_cast<uint32_t*>(&h1));
    *reinterpret_cast<uint2*>(&g_xhi[o]) = hp;
    *reinterpret_cast<uint32_t*>(&g_xa8[o]) = pack4(a8[0], a8[1], a8[2], a8[3]);
    *reinterpret_cast<uint32_t*>(&g_xl8[o]) = pack4(l8[0], l8[1], l8[2], l8[3]);
}

// ---------------------------------------------------------------------------
// Pre-pass: W1 -> whi (fp16 of w*1024), w8 (rn(w*4096)), wl8 (rn(w_lo*8))
// w_lo = (w*1024 - whi)*2048
// ---------------------------------------------------------------------------
__global__ __launch_bounds__(256)
void split_w_kernel(const float* __restrict__ W1)
{
    const int idx = blockIdx.x * blockDim.x + threadIdx.x;  // NHID*K4
    if (idx >= NHID * K4) return;
    const int hrow = idx / K4;
    const int k4   = idx - hrow * K4;
    const int k    = k4 * 4;
    float4 v = make_float4(0.f, 0.f, 0.f, 0.f);
    if (k < NIN)
        v = *reinterpret_cast<const float4*>(W1 + (size_t)hrow * NIN + k);
    float vv[4] = {v.x, v.y, v.z, v.w};
    __half h[4]; int w8[4], wl8[4];
#pragma unroll
    for (int i = 0; i < 4; i++) {
        float ws = vv[i] * 1024.f;
        h[i] = __float2half_rn(ws);
        float wlo = (ws - __half2float(h[i])) * 2048.f;
        w8[i]  = s8cl(vv[i] * 4096.f);
        wl8[i] = s8cl(wlo * 8.f);
    }
    const size_t o = (size_t)hrow * NINP + k;
    __half2 h0 = __halves2half2(h[0], h[1]);
    __half2 h1 = __halves2half2(h[2], h[3]);
    uint2 hp = make_uint2(*reinterpret_cast<uint32_t*>(&h0),
                          *reinterpret_cast<uint32_t*>(&h1));
    *reinterpret_cast<uint2*>(&g_whi[o]) = hp;
    *reinterpret_cast<uint32_t*>(&g_w8[o])  = pack4(w8[0], w8[1], w8[2], w8[3]);
    *reinterpret_cast<uint32_t*>(&g_wl8[o]) = pack4(wl8[0], wl8[1], wl8[2], wl8[3]);
}

// C[h] = (sum_k wl8[h,k]) * 2^-25   (offset correction for a = (a8+64)/128)
__global__ __launch_bounds__(256)
void rowsum_w_kernel()
{
    const int hrow = blockIdx.x * 8 + (threadIdx.x >> 5);
    const int lane = threadIdx.x & 31;
    const uint32_t* p = reinterpret_cast<const uint32_t*>(g_wl8 + (size_t)hrow * NINP);
    int s = 0;
    for (int i = lane; i < NINP / 4; i += 32)
        s = __dp4a((int)p[i], 0x01010101, s);
#pragma unroll
    for (int o = 16; o > 0; o >>= 1)
        s += __shfl_xor_sync(0xffffffffu, s, o);
    if (lane == 0)
        g_ch[hrow] = (float)s * 2.98023223876953125e-8f;   // 2^-25
}

// ---------------------------------------------------------------------------
// GEMM1: cur1 = S_hh/1024 + cross*2^-31 + C[h]
//   hh:    fp16 m16n8k16, f32 accum, chunk-local accT + RN drain
//   cross: int8 m16n8k32, s32 accum (exact): sum(a8*wl8 + xl8*w8)
// CTA 128x128, k-chunk 32, cp.async 3-stage pipeline, B-frags hoisted.
// ---------------------------------------------------------------------------
#define KCH      37
#define ROWB16   80
#define ROWB8    48
#define OFF_AHI  0
#define OFF_BHI  10240
#define OFF_A8   20480
#define OFF_AL8  26624
#define OFF_W8   32768
#define OFF_WL8  38912
#define STAGE_SB 45056
#define NSTAGE   3
#define SMEM_DYN (NSTAGE * STAGE_SB)   // 135168

__device__ __forceinline__ void cpa16(uint32_t dst, const void* src) {
    asm volatile("cp.async.cg.shared.global [%0], [%1], 16;"
                 :: "r"(dst), "l"(src) : "memory");
}
#define CPA_COMMIT() asm volatile("cp.async.commit_group;" ::: "memory")
#define CPA_WAIT(n)  asm volatile("cp.async.wait_group %0;" :: "n"(n) : "memory")

__device__ __forceinline__ void ldm_x4(uint32_t addr, uint32_t& r0, uint32_t& r1,
                                       uint32_t& r2, uint32_t& r3) {
    asm volatile("ldmatrix.sync.aligned.m8n8.x4.shared.b16 {%0,%1,%2,%3}, [%4];"
                 : "=r"(r0), "=r"(r1), "=r"(r2), "=r"(r3) : "r"(addr));
}

__device__ __forceinline__ void mma_f16(float* c, const uint32_t* a, const uint32_t* b) {
    asm volatile(
        "mma.sync.aligned.m16n8k16.row.col.f32.f16.f16.f32 "
        "{%0,%1,%2,%3}, {%4,%5,%6,%7}, {%8,%9}, {%0,%1,%2,%3};"
        : "+f"(c[0]), "+f"(c[1]), "+f"(c[2]), "+f"(c[3])
        : "r"(a[0]), "r"(a[1]), "r"(a[2]), "r"(a[3]), "r"(b[0]), "r"(b[1]));
}

__device__ __forceinline__ void mma_s8(int* c, const uint32_t* a, const uint32_t* b) {
    asm volatile(
        "mma.sync.aligned.m16n8k32.row.col.s32.s8.s8.s32 "
        "{%0,%1,%2,%3}, {%4,%5,%6,%7}, {%8,%9}, {%0,%1,%2,%3};"
        : "+r"(c[0]), "+r"(c[1]), "+r"(c[2]), "+r"(c[3])
        : "r"(a[0]), "r"(a[1]), "r"(a[2]), "r"(a[3]), "r"(b[0]), "r"(b[1]));
}

__global__ __launch_bounds__(256, 1)
void gemm1_mma_kernel()
{
    extern __shared__ char smem[];
    uint32_t sbase;
    asm("{ .reg .u64 t; cvta.to.shared.u64 t, %1; cvt.u32.u64 %0, t; }"
        : "=r"(sbase) : "l"(smem));

    const int tid   = threadIdx.x;
    const int lane  = tid & 31;
    const int w     = tid >> 5;
    const int mtile = blockIdx.y;
    const int ntile = blockIdx.x;
    const int MW    = (w & 1) * 64;
    const int NW    = (w >> 1) * 32;
    const int m0    = mtile * 128;
    const int n0    = ntile * 128;

    // cp.async plan: 8 x 16B per thread per chunk
    const char* srcs[8];
    uint32_t doff[8];
#pragma unroll
    for (int i = 0; i < 8; i++) {
        const int idx = i * 256 + tid;      // 0..2047
        if (idx < 512) {                    // Ahi fp16: r 0..127, c 0..3
            const int r = idx >> 2, c = idx & 3;
            srcs[i] = (const char*)(g_xhi + (size_t)(m0 + r) * NINP) + c * 16;
            doff[i] = (uint32_t)(OFF_AHI + r * ROWB16 + c * 16);
        } else if (idx < 1024) {            // Bhi fp16
            const int j = idx - 512, r = j >> 2, c = j & 3;
            srcs[i] = (const char*)(g_whi + (size_t)(n0 + r) * NINP) + c * 16;
            doff[i] = (uint32_t)(OFF_BHI + r * ROWB16 + c * 16);
        } else if (idx < 1280) {            // xa8
            const int j = idx - 1024, r = j >> 1, c = j & 1;
            srcs[i] = (const char*)(g_xa8 + (size_t)(m0 + r) * NINP) + c * 16;
            doff[i] = (uint32_t)(OFF_A8 + r * ROWB8 + c * 16);
        } else if (idx < 1536) {            // xl8
            const int j = idx - 1280, r = j >> 1, c = j & 1;
            srcs[i] = (const char*)(g_xl8 + (size_t)(m0 + r) * NINP) + c * 16;
            doff[i] = (uint32_t)(OFF_AL8 + r * ROWB8 + c * 16);
        } else if (idx < 1792) {            // w8
            const int j = idx - 1536, r = j >> 1, c = j & 1;
            srcs[i] = (const char*)(g_w8 + (size_t)(n0 + r) * NINP) + c * 16;
            doff[i] = (uint32_t)(OFF_W8 + r * ROWB8 + c * 16);
        } else {                            // wl8
            const int j = idx - 1792, r = j >> 1, c = j & 1;
            srcs[i] = (const char*)(g_wl8 + (size_t)(n0 + r) * NINP) + c * 16;
            doff[i] = (uint32_t)(OFF_WL8 + r * ROWB8 + c * 16);
        }
    }

    float acc[4][4][4];
#pragma unroll
    for (int mi = 0; mi < 4; mi++)
#pragma unroll
        for (int nj = 0; nj < 4; nj++)
#pragma unroll
            for (int q = 0; q < 4; q++) acc[mi][nj][q] = 0.f;

    // fragment lane addressing
    const int sub = lane >> 3;
    const int l7  = lane & 7;
    const int a_r = MW + (sub & 1) * 8 + l7;          // f16 A
    const int a_c = (sub >> 1) * 8;
    const int b_r = NW + (sub >> 1) * 8 + l7;         // f16 B
    const int b_c = (sub & 1) * 8;
    const int a8_r = MW + ((lane >> 3) & 1) * 8 + l7; // s8 A
    const int a8_k = ((lane >> 4) & 1) * 16;
    const int b8_r = NW + ((lane >> 4) & 1) * 8 + l7; // s8 B
    const int b8_k = ((lane >> 3) & 1) * 16;

    auto issue = [&]() {
#pragma unroll
        for (int i = 0; i < 8; i++) {
            const int stage_off = 0;  // dst handled below
            (void)stage_off;
        }
    };
    (void)issue;

    // explicit issue with per-chunk advance
    int kbyte16 = 0, kbyte8 = 0;   // byte advance for fp16 / s8 sources
    auto issue_chunk = [&](int c) {
        const uint32_t sb = sbase + (uint32_t)(c % NSTAGE) * STAGE_SB;
        const int o16 = c * 64;    // 32 halfs
        const int o8  = c * 32;    // 32 bytes
#pragma unroll
        for (int i = 0; i < 8; i++) {
            const int adv = (i < 4) ? o16 : o8;
            cpa16(sb + doff[i], srcs[i] + adv);
        }
        CPA_COMMIT();
        (void)kbyte16; (void)kbyte8;
    };

    issue_chunk(0); issue_chunk(1); issue_chunk(2);

    for (int c = 0; c < KCH; c++) {
        CPA_WAIT(2);
        __syncthreads();

        const uint32_t stg = sbase + (uint32_t)(c % NSTAGE) * STAGE_SB;

        // hoisted B fragments
        uint32_t bh[2][4][2];          // [ks][nj][reg]
#pragma unroll
        for (int ks = 0; ks < 2; ks++)
#pragma unroll
            for (int nt = 0; nt < 2; nt++) {
                const uint32_t bo = stg + OFF_BHI +
                    (uint32_t)((b_r + nt * 16) * ROWB16 + (ks * 16 + b_c) * 2);
                uint32_t r0, r1, r2, r3;
                ldm_x4(bo, r0, r1, r2, r3);
                bh[ks][nt * 2][0] = r0; bh[ks][nt * 2][1] = r1;
                bh[ks][nt * 2 + 1][0] = r2; bh[ks][nt * 2 + 1][1] = r3;
            }
        uint32_t wf[4][2], wlf[4][2];  // s8 B frags: w8, wl8
#pragma unroll
        for (int nt8 = 0; nt8 < 2; nt8++) {
            const uint32_t rowoff = (uint32_t)((b8_r + nt8 * 16) * ROWB8 + b8_k);
            uint32_t r0, r1, r2, r3;
            ldm_x4(stg + OFF_W8 + rowoff, r0, r1, r2, r3);
            wf[nt8 * 2][0] = r0; wf[nt8 * 2][1] = r1;
            wf[nt8 * 2 + 1][0] = r2; wf[nt8 * 2 + 1][1] = r3;
            ldm_x4(stg + OFF_WL8 + rowoff, r0, r1, r2, r3);
            wlf[nt8 * 2][0] = r0; wlf[nt8 * 2][1] = r1;
            wlf[nt8 * 2 + 1][0] = r2; wlf[nt8 * 2 + 1][1] = r3;
        }

#pragma unroll
        for (int mh = 0; mh < 4; mh++) {
            float accT[4][4];
            int   accC[4][4];
#pragma unroll
            for (int nj = 0; nj < 4; nj++)
#pragma unroll
                for (int q = 0; q < 4; q++) { accT[nj][q] = 0.f; accC[nj][q] = 0; }

            // fp16 hh
#pragma unroll
            for (int ks = 0; ks < 2; ks++) {
                uint32_t ah[4];
                const uint32_t ao = stg + OFF_AHI +
                    (uint32_t)((a_r + mh * 16) * ROWB16 + (ks * 16 + a_c) * 2);
                ldm_x4(ao, ah[0], ah[1], ah[2], ah[3]);
#pragma unroll
                for (int nj = 0; nj < 4; nj++)
                    mma_f16(accT[nj], ah, bh[ks][nj]);
            }
            // int8 cross (one K=32 step)
            {
                uint32_t a8[4], al8[4];
                const uint32_t rowoff = (uint32_t)((a8_r + mh * 16) * ROWB8 + a8_k);
                ldm_x4(stg + OFF_A8 + rowoff, a8[0], a8[1], a8[2], a8[3]);
                ldm_x4(stg + OFF_AL8 + rowoff, al8[0], al8[1], al8[2], al8[3]);
#pragma unroll
                for (int nj = 0; nj < 4; nj++) {
                    mma_s8(accC[nj], a8, wlf[nj]);   // a8  * wl8
                    mma_s8(accC[nj], al8, wf[nj]);   // xl8 * w8
                }
            }
            // RN drain: acc in (w*1024)-units; cross unit 2^-31 * 1024 = 2^-21
#pragma unroll
            for (int nj = 0; nj < 4; nj++)
#pragma unroll
                for (int q = 0; q < 4; q++)
                    acc[mh][nj][q] += accT[nj][q]
                                    + (float)accC[nj][q] * 4.76837158203125e-7f;
        }

        __syncthreads();
        if (c + 3 < KCH) issue_chunk(c + 3);
    }

    // epilogue: /1024 + C[h]
    const int mbase = m0 + MW + (lane >> 2);
    const int nbase = n0 + NW + (lane & 3) * 2;
    const float S = 1.f / 1024.f;
#pragma unroll
    for (int mi = 0; mi < 4; mi++)
#pragma unroll
        for (int nj = 0; nj < 4; nj++) {
            const int r = mbase + mi * 16;
            const int col = nbase + nj * 8;
            const float c0 = g_ch[col], c1 = g_ch[col + 1];
            *reinterpret_cast<float2*>(&g_cur[(size_t)r * NHID + col]) =
                make_float2(acc[mi][nj][0] * S + c0, acc[mi][nj][1] * S + c1);
            *reinterpret_cast<float2*>(&g_cur[(size_t)(r + 8) * NHID + col]) =
                make_float2(acc[mi][nj][2] * S + c0, acc[mi][nj][3] * S + c1);
        }
}

// ---------------------------------------------------------------------------
// Kernel: per-(b,h) LIF scan; packed spike bits via ballot.
// ---------------------------------------------------------------------------
__global__ __launch_bounds__(256)
void spike_scan_kernel()
{
    const int tid  = blockIdx.x * blockDim.x + threadIdx.x;
    const int BH   = B_ * NHID;
    const int widx = tid >> 5;
    float mem1 = 0.f;

    for (int t = 0; t < T_; t++) {
        const float c = g_cur[(size_t)t * BH + tid];
        const float reset = (mem1 > THR) ? THR : 0.f;
        mem1 = BETA * mem1 + c - reset;
        const unsigned bal = __ballot_sync(0xffffffffu, (mem1 - THR) > 0.f);
        if ((tid & 31) == 0)
            g_spk[(size_t)t * (BH / 32) + widx] = bal;
    }
}

// ---------------------------------------------------------------------------
// Kernel: Y[t,b,o] = sum_h spk * W2[o,h]
// ---------------------------------------------------------------------------
__global__ __launch_bounds__(256)
void ygemm_kernel(const float* __restrict__ W2)
{
    __shared__ float w2s[NOUT * NHID];
    for (int i = threadIdx.x; i < NOUT * NHID; i += blockDim.x)
        w2s[i] = W2[i];
    __syncthreads();

    const int row = blockIdx.x * blockDim.x + threadIdx.x;
    float acc[NOUT];
#pragma unroll
    for (int o = 0; o < NOUT; o++) acc[o] = 0.f;

    const unsigned* sp = g_spk + (size_t)row * (NHID / 32);
#pragma unroll 4
    for (int wd = 0; wd < NHID / 32; wd++) {
        unsigned bits = sp[wd];
        while (bits) {
            const int j = __ffs(bits) - 1;
            bits &= bits - 1;
            const int h = (wd << 5) + j;
#pragma unroll
            for (int o = 0; o < NOUT; o++)
                acc[o] += w2s[o * NHID + h];
        }
    }

    float* yp = g_y + (size_t)row * NOUT;
#pragma unroll
    for (int o = 0; o < NOUT; o++) yp[o] = acc[o];
}

// ---------------------------------------------------------------------------
// Kernel: mem2 leaky scan, write output [T, B, NOUT]
// ---------------------------------------------------------------------------
__global__ __launch_bounds__(256)
void out_scan_kernel(float* __restrict__ out)
{
    const int idx = blockIdx.x * blockDim.x + threadIdx.x;
    if (idx >= B_ * NOUT) return;
    const int BO = B_ * NOUT;
    float mem2 = 0.f;
#pragma unroll
    for (int tb = 0; tb < T_; tb += 16) {
        float v[16];
#pragma unroll
        for (int u = 0; u < 16; u++)
            v[u] = g_y[(size_t)(tb + u) * BO + idx];
#pragma unroll
        for (int u = 0; u < 16; u++) {
            mem2 = BETA * mem2 + v[u];
            out[(size_t)(tb + u) * BO + idx] = mem2;
        }
    }
}

// ---------------------------------------------------------------------------
extern "C" void kernel_launch(void* const* d_in, const int* in_sizes, int n_in,
                              void* d_out, int out_size)
{
    const float* x  = (const float*)d_in[0];
    const float* W1 = (const float*)d_in[1];
    const float* W2 = (const float*)d_in[2];
    float* out = (float*)d_out;

    cudaFuncSetAttribute(gemm1_mma_kernel,
                         cudaFuncAttributeMaxDynamicSharedMemorySize, SMEM_DYN);

    split_x_kernel<<<(M_ * K4) / 256, 256>>>(x);
    split_w_kernel<<<(NHID * K4 + 255) / 256, 256>>>(W1);
    rowsum_w_kernel<<<NHID / 8, 256>>>();

    dim3 grid1(NHID / 128, M_ / 128);
    gemm1_mma_kernel<<<grid1, 256, SMEM_DYN>>>();

    spike_scan_kernel<<<(B_ * NHID) / 256, 256>>>();

    ygemm_kernel<<<M_ / 256, 256>>>(W2);

    out_scan_kernel<<<(B_ * NOUT + 255) / 256, 256>>>(out);
}

// round 13
// speedup vs baseline: 1.1000x; 1.1000x over previous
#include <cuda_runtime.h>
#include <cuda_fp16.h>
#include <cstdint>

// Problem constants
#define B_    256
#define T_    128
#define NIN   1156
#define NHID  1024
#define NOUT  10
#define M_    (T_ * B_)
#define BETA  0.95f
#define THR   1.0f
#define NINP  1184                 // NIN padded to 37*32 (zero-filled)
#define K4    (NINP / 4)           // 296

// Scratch
__device__ float    g_cur[(size_t)M_ * NHID];
__device__ unsigned g_spk[(size_t)M_ * NHID / 32];
__device__ float    g_y  [(size_t)M_ * NOUT];
__device__ __half   g_xhi[(size_t)M_ * NINP];
__device__ __half   g_xlo[(size_t)M_ * NINP];
__device__ __half   g_whi[(size_t)NHID * NINP];
__device__ __half   g_wlo[(size_t)NHID * NINP];

// ---------------------------------------------------------------------------
// fp16 hi/lo split: v = hi + lo/2048 (lo scaled into normal range)
// ---------------------------------------------------------------------------
__device__ __forceinline__ void split_pack(float v0, float v1,
                                           uint32_t& hi, uint32_t& lo) {
    __half h0 = __float2half_rn(v0);
    __half h1 = __float2half_rn(v1);
    __half l0 = __float2half_rn((v0 - __half2float(h0)) * 2048.f);
    __half l1 = __float2half_rn((v1 - __half2float(h1)) * 2048.f);
    __half2 hp = __halves2half2(h0, h1);
    __half2 lp = __halves2half2(l0, l1);
    hi = *reinterpret_cast<uint32_t*>(&hp);
    lo = *reinterpret_cast<uint32_t*>(&lp);
}

// Pre-pass: X [B,T,NIN] fp32 -> g_xhi/g_xlo [m, NINP] fp16, m = t*256+b
__global__ __launch_bounds__(256)
void split_x_kernel(const float* __restrict__ x)
{
    const int idx = blockIdx.x * blockDim.x + threadIdx.x;  // M_*K4
    const int m  = idx / K4;
    const int k4 = idx - m * K4;
    const int k  = k4 * 4;
    const int t  = m >> 8;
    const int b  = m & 255;
    float4 v = make_float4(0.f, 0.f, 0.f, 0.f);
    if (k < NIN)
        v = *reinterpret_cast<const float4*>(x + ((size_t)b * T_ + t) * NIN + k);
    uint2 hi, lo;
    split_pack(v.x, v.y, hi.x, lo.x);
    split_pack(v.z, v.w, hi.y, lo.y);
    const size_t o = (size_t)m * NINP + k;
    *reinterpret_cast<uint2*>(&g_xhi[o]) = hi;
    *reinterpret_cast<uint2*>(&g_xlo[o]) = lo;
}

// Pre-pass: W1 [NHID,NIN] fp32 * 1024 -> g_whi/g_wlo fp16
__global__ __launch_bounds__(256)
void split_w_kernel(const float* __restrict__ W1)
{
    const int idx = blockIdx.x * blockDim.x + threadIdx.x;  // NHID*K4
    if (idx >= NHID * K4) return;
    const int h  = idx / K4;
    const int k4 = idx - h * K4;
    const int k  = k4 * 4;
    float4 v = make_float4(0.f, 0.f, 0.f, 0.f);
    if (k < NIN)
        v = *reinterpret_cast<const float4*>(W1 + (size_t)h * NIN + k);
    uint2 hi, lo;
    split_pack(v.x * 1024.f, v.y * 1024.f, hi.x, lo.x);
    split_pack(v.z * 1024.f, v.w * 1024.f, hi.y, lo.y);
    const size_t o = (size_t)h * NINP + k;
    *reinterpret_cast<uint2*>(&g_whi[o]) = hi;
    *reinterpret_cast<uint2*>(&g_wlo[o]) = lo;
}

// ---------------------------------------------------------------------------
// GEMM1: CTA tile 128(M) x 64(N), 8 warps as 4(M) x 2(N), warp tile 32x32.
// fp16 hi/lo, cur1 = (S_hh + S_c/2048)/1024. Chunk-local accT + RN drain.
// cp.async 3-stage pipeline. 2 CTAs/SM.
// ---------------------------------------------------------------------------
#define KCH      37
#define ROWB     80                // bytes per smem row (32 fp16 + 8 pad)
#define OFF_AHI  0                 // 128 rows
#define OFF_ALO  10240
#define OFF_BHI  20480             // 64 rows
#define OFF_BLO  25600
#define STAGE_SB 30720
#define NSTAGE   3
#define SMEM_DYN (NSTAGE * STAGE_SB)   // 92160 B

__device__ __forceinline__ void cpa16(uint32_t dst, const void* src) {
    asm volatile("cp.async.cg.shared.global [%0], [%1], 16;"
                 :: "r"(dst), "l"(src) : "memory");
}
#define CPA_COMMIT() asm volatile("cp.async.commit_group;" ::: "memory")
#define CPA_WAIT(n)  asm volatile("cp.async.wait_group %0;" :: "n"(n) : "memory")

__device__ __forceinline__ void ldm_x4(uint32_t addr, uint32_t& r0, uint32_t& r1,
                                       uint32_t& r2, uint32_t& r3) {
    asm volatile("ldmatrix.sync.aligned.m8n8.x4.shared.b16 {%0,%1,%2,%3}, [%4];"
                 : "=r"(r0), "=r"(r1), "=r"(r2), "=r"(r3) : "r"(addr));
}

__device__ __forceinline__ void mma_f16(float* c, const uint32_t* a, const uint32_t* b) {
    asm volatile(
        "mma.sync.aligned.m16n8k16.row.col.f32.f16.f16.f32 "
        "{%0,%1,%2,%3}, {%4,%5,%6,%7}, {%8,%9}, {%0,%1,%2,%3};"
        : "+f"(c[0]), "+f"(c[1]), "+f"(c[2]), "+f"(c[3])
        : "r"(a[0]), "r"(a[1]), "r"(a[2]), "r"(a[3]), "r"(b[0]), "r"(b[1]));
}

__global__ __launch_bounds__(256, 2)
void gemm1_mma_kernel()
{
    extern __shared__ char smem[];
    uint32_t sbase;
    asm("{ .reg .u64 t; cvta.to.shared.u64 t, %1; cvt.u32.u64 %0, t; }"
        : "=r"(sbase) : "l"(smem));

    const int tid   = threadIdx.x;
    const int lane  = tid & 31;
    const int w     = tid >> 5;
    const int mtile = blockIdx.y;     // 0..255
    const int ntile = blockIdx.x;     // 0..15
    const int MW    = (w >> 1) * 32;  // warp m offset (4 warps)
    const int NW    = (w & 1) * 32;   // warp n offset (2 warps)
    const int m0    = mtile * 128;
    const int n0    = ntile * 64;

    // cp.async plan: 6 x 16B per thread per chunk (1536 chunks/stage)
    const char* srcs[6];
    uint32_t doff[6];
#pragma unroll
    for (int i = 0; i < 6; i++) {
        const int idx = i * 256 + tid;      // 0..1535
        if (idx < 512) {                    // Ahi: r 0..127, c 0..3
            const int r = idx >> 2, c = idx & 3;
            srcs[i] = (const char*)(g_xhi + (size_t)(m0 + r) * NINP) + c * 16;
            doff[i] = (uint32_t)(OFF_AHI + r * ROWB + c * 16);
        } else if (idx < 1024) {            // Alo
            const int j = idx - 512, r = j >> 2, c = j & 3;
            srcs[i] = (const char*)(g_xlo + (size_t)(m0 + r) * NINP) + c * 16;
            doff[i] = (uint32_t)(OFF_ALO + r * ROWB + c * 16);
        } else if (idx < 1280) {            // Bhi: r 0..63
            const int j = idx - 1024, r = j >> 2, c = j & 3;
            srcs[i] = (const char*)(g_whi + (size_t)(n0 + r) * NINP) + c * 16;
            doff[i] = (uint32_t)(OFF_BHI + r * ROWB + c * 16);
        } else {                            // Blo
            const int j = idx - 1280, r = j >> 2, c = j & 3;
            srcs[i] = (const char*)(g_wlo + (size_t)(n0 + r) * NINP) + c * 16;
            doff[i] = (uint32_t)(OFF_BLO + r * ROWB + c * 16);
        }
    }

    float acc[2][4][4];                 // persistent (RN adds only)
#pragma unroll
    for (int mi = 0; mi < 2; mi++)
#pragma unroll
        for (int nj = 0; nj < 4; nj++)
#pragma unroll
            for (int q = 0; q < 4; q++) acc[mi][nj][q] = 0.f;

    // ldmatrix lane addressing
    const int sub = lane >> 3;
    const int l7  = lane & 7;
    const int a_r = MW + (sub & 1) * 8 + l7;
    const int a_c = (sub >> 1) * 8;
    const int b_r = NW + (sub >> 1) * 8 + l7;
    const int b_c = (sub & 1) * 8;

    auto issue_chunk = [&](int c) {
        const uint32_t sb = sbase + (uint32_t)(c % NSTAGE) * STAGE_SB;
        const int o16 = c * 64;         // 32 halfs = 64 B
#pragma unroll
        for (int i = 0; i < 6; i++)
            cpa16(sb + doff[i], srcs[i] + o16);
        CPA_COMMIT();
    };

    issue_chunk(0); issue_chunk(1); issue_chunk(2);

    for (int c = 0; c < KCH; c++) {
        CPA_WAIT(2);
        __syncthreads();

        const uint32_t stg = sbase + (uint32_t)(c % NSTAGE) * STAGE_SB;

#pragma unroll
        for (int mi = 0; mi < 2; mi++) {
            float accT[2][4][4];        // [group hh / c][nj][q]
#pragma unroll
            for (int g = 0; g < 2; g++)
#pragma unroll
                for (int nj = 0; nj < 4; nj++)
#pragma unroll
                    for (int q = 0; q < 4; q++) accT[g][nj][q] = 0.f;

#pragma unroll
            for (int ks = 0; ks < 2; ks++) {
                uint32_t ah[4], al[4], bh[4][2], bl[4][2];
                const uint32_t ao = stg +
                    (uint32_t)((a_r + mi * 16) * ROWB + (ks * 16 + a_c) * 2);
                ldm_x4(ao + OFF_AHI, ah[0], ah[1], ah[2], ah[3]);
                ldm_x4(ao + OFF_ALO, al[0], al[1], al[2], al[3]);
#pragma unroll
                for (int nt = 0; nt < 2; nt++) {
                    const uint32_t bo = stg +
                        (uint32_t)((b_r + nt * 16) * ROWB + (ks * 16 + b_c) * 2);
                    uint32_t r0, r1, r2, r3;
                    ldm_x4(bo + OFF_BHI, r0, r1, r2, r3);
                    bh[nt * 2][0] = r0; bh[nt * 2][1] = r1;
                    bh[nt * 2 + 1][0] = r2; bh[nt * 2 + 1][1] = r3;
                    ldm_x4(bo + OFF_BLO, r0, r1, r2, r3);
                    bl[nt * 2][0] = r0; bl[nt * 2][1] = r1;
                    bl[nt * 2 + 1][0] = r2; bl[nt * 2 + 1][1] = r3;
                }
#pragma unroll
                for (int nj = 0; nj < 4; nj++) {
                    mma_f16(accT[0][nj], ah, bh[nj]);
                    mma_f16(accT[1][nj], ah, bl[nj]);
                    mma_f16(accT[1][nj], al, bh[nj]);
                }
            }
            // RN drain: acc += hh + c/2048
#pragma unroll
            for (int nj = 0; nj < 4; nj++)
#pragma unroll
                for (int q = 0; q < 4; q++)
                    acc[mi][nj][q] += accT[0][nj][q]
                                    + accT[1][nj][q] * (1.f / 2048.f);
        }

        __syncthreads();
        if (c + 3 < KCH) issue_chunk(c + 3);
    }

    // epilogue: undo W scale
    const int mbase = m0 + MW + (lane >> 2);
    const int nbase = n0 + NW + (lane & 3) * 2;
    const float S = 1.f / 1024.f;
#pragma unroll
    for (int mi = 0; mi < 2; mi++)
#pragma unroll
        for (int nj = 0; nj < 4; nj++) {
            const int r = mbase + mi * 16;
            const int col = nbase + nj * 8;
            *reinterpret_cast<float2*>(&g_cur[(size_t)r * NHID + col]) =
                make_float2(acc[mi][nj][0] * S, acc[mi][nj][1] * S);
            *reinterpret_cast<float2*>(&g_cur[(size_t)(r + 8) * NHID + col]) =
                make_float2(acc[mi][nj][2] * S, acc[mi][nj][3] * S);
        }
}

// ---------------------------------------------------------------------------
// Kernel: per-(b,h) LIF scan; t unrolled x4 for MLP; ballot-packed spikes.
// ---------------------------------------------------------------------------
__global__ __launch_bounds__(256)
void spike_scan_kernel()
{
    const int tid  = blockIdx.x * blockDim.x + threadIdx.x;
    const int BH   = B_ * NHID;
    const int widx = tid >> 5;
    float mem1 = 0.f;

#pragma unroll 2
    for (int tb = 0; tb < T_; tb += 4) {
        float cv[4];
#pragma unroll
        for (int u = 0; u < 4; u++)
            cv[u] = g_cur[(size_t)(tb + u) * BH + tid];
#pragma unroll
        for (int u = 0; u < 4; u++) {
            const float reset = (mem1 > THR) ? THR : 0.f;
            mem1 = BETA * mem1 + cv[u] - reset;
            const unsigned bal = __ballot_sync(0xffffffffu, (mem1 - THR) > 0.f);
            if ((tid & 31) == 0)
                g_spk[(size_t)(tb + u) * (BH / 32) + widx] = bal;
        }
    }
}

// ---------------------------------------------------------------------------
// Kernel: Y[t,b,o] = sum_h spk * W2[o,h]
// ---------------------------------------------------------------------------
__global__ __launch_bounds__(256)
void ygemm_kernel(const float* __restrict__ W2)
{
    __shared__ float w2s[NOUT * NHID];
    for (int i = threadIdx.x; i < NOUT * NHID; i += blockDim.x)
        w2s[i] = W2[i];
    __syncthreads();

    const int row = blockIdx.x * blockDim.x + threadIdx.x;
    float acc[NOUT];
#pragma unroll
    for (int o = 0; o < NOUT; o++) acc[o] = 0.f;

    const unsigned* sp = g_spk + (size_t)row * (NHID / 32);
#pragma unroll 4
    for (int wd = 0; wd < NHID / 32; wd++) {
        unsigned bits = sp[wd];
        while (bits) {
            const int j = __ffs(bits) - 1;
            bits &= bits - 1;
            const int h = (wd << 5) + j;
#pragma unroll
            for (int o = 0; o < NOUT; o++)
                acc[o] += w2s[o * NHID + h];
        }
    }

    float* yp = g_y + (size_t)row * NOUT;
#pragma unroll
    for (int o = 0; o < NOUT; o++) yp[o] = acc[o];
}

// ---------------------------------------------------------------------------
// Kernel: mem2 leaky scan, write output [T, B, NOUT]
// ---------------------------------------------------------------------------
__global__ __launch_bounds__(256)
void out_scan_kernel(float* __restrict__ out)
{
    const int idx = blockIdx.x * blockDim.x + threadIdx.x;
    if (idx >= B_ * NOUT) return;
    const int BO = B_ * NOUT;
    float mem2 = 0.f;
#pragma unroll
    for (int tb = 0; tb < T_; tb += 16) {
        float v[16];
#pragma unroll
        for (int u = 0; u < 16; u++)
            v[u] = g_y[(size_t)(tb + u) * BO + idx];
#pragma unroll
        for (int u = 0; u < 16; u++) {
            mem2 = BETA * mem2 + v[u];
            out[(size_t)(tb + u) * BO + idx] = mem2;
        }
    }
}

// ---------------------------------------------------------------------------
extern "C" void kernel_launch(void* const* d_in, const int* in_sizes, int n_in,
                              void* d_out, int out_size)
{
    const float* x  = (const float*)d_in[0];
    const float* W1 = (const float*)d_in[1];
    const float* W2 = (const float*)d_in[2];
    float* out = (float*)d_out;

    cudaFuncSetAttribute(gemm1_mma_kernel,
                         cudaFuncAttributeMaxDynamicSharedMemorySize, SMEM_DYN);

    split_x_kernel<<<(M_ * K4) / 256, 256>>>(x);
    split_w_kernel<<<(NHID * K4 + 255) / 256, 256>>>(W1);

    dim3 grid1(NHID / 64, M_ / 128);           // (16, 256)
    gemm1_mma_kernel<<<grid1, 256, SMEM_DYN>>>();

    spike_scan_kernel<<<(B_ * NHID) / 256, 256>>>();

    ygemm_kernel<<<M_ / 256, 256>>>(W2);

    out_scan_kernel<<<(B_ * NOUT + 255) / 256, 256>>>(out);
}

// round 14
// speedup vs baseline: 1.1338x; 1.0307x over previous
#include <cuda_runtime.h>
#include <cuda_fp16.h>
#include <cstdint>

// Problem constants
#define B_    256
#define T_    128
#define NIN   1156
#define NHID  1024
#define NOUT  10
#define M_    (T_ * B_)
#define BETA  0.95f
#define THR   1.0f
#define NINP  1184                 // NIN padded to 37*32 (zero-filled)
#define K4    (NINP / 4)           // 296

// Scratch
__device__ float    g_cur[(size_t)M_ * NHID];
__device__ unsigned g_spk[(size_t)M_ * NHID / 32];
__device__ float    g_y  [(size_t)M_ * NOUT];
__device__ __half   g_whi[(size_t)NHID * NINP];
__device__ __half   g_wlo[(size_t)NHID * NINP];

// ---------------------------------------------------------------------------
// fp16 hi/lo split: v = hi + lo/2048 (lo scaled into normal range)
// ---------------------------------------------------------------------------
__device__ __forceinline__ void split_pack(float v0, float v1,
                                           uint32_t& hi, uint32_t& lo) {
    __half h0 = __float2half_rn(v0);
    __half h1 = __float2half_rn(v1);
    __half l0 = __float2half_rn((v0 - __half2float(h0)) * 2048.f);
    __half l1 = __float2half_rn((v1 - __half2float(h1)) * 2048.f);
    __half2 hp = __halves2half2(h0, h1);
    __half2 lp = __halves2half2(l0, l1);
    hi = *reinterpret_cast<uint32_t*>(&hp);
    lo = *reinterpret_cast<uint32_t*>(&lp);
}

// Pre-pass (tiny): W1 [NHID,NIN] fp32 * 1024 -> g_whi/g_wlo fp16, K padded
__global__ __launch_bounds__(256)
void split_w_kernel(const float* __restrict__ W1)
{
    const int idx = blockIdx.x * blockDim.x + threadIdx.x;  // NHID*K4
    if (idx >= NHID * K4) return;
    const int h  = idx / K4;
    const int k4 = idx - h * K4;
    const int k  = k4 * 4;
    float4 v = make_float4(0.f, 0.f, 0.f, 0.f);
    if (k < NIN)
        v = *reinterpret_cast<const float4*>(W1 + (size_t)h * NIN + k);
    uint2 hi, lo;
    split_pack(v.x * 1024.f, v.y * 1024.f, hi.x, lo.x);
    split_pack(v.z * 1024.f, v.w * 1024.f, hi.y, lo.y);
    const size_t o = (size_t)h * NINP + k;
    *reinterpret_cast<uint2*>(&g_whi[o]) = hi;
    *reinterpret_cast<uint2*>(&g_wlo[o]) = lo;
}

// ---------------------------------------------------------------------------
// GEMM1: CTA 128(M) x 64(N), 8 warps 4(M)x2(N), warp tile 32x32.
// X split fused in-kernel (LDG fp32 -> split -> STS), W via cp.async from
// pre-split fp16. Chunk-local accT + RN drain. Double-buffered, 2 CTAs/SM.
// cur1 = (S_hh + S_c/2048)/1024.
// ---------------------------------------------------------------------------
#define KCH      37
#define ROWB     80                // bytes per smem row (32 fp16 + 8 pad)
#define OFF_AHI  0                 // 128 rows
#define OFF_ALO  10240
#define OFF_BHI  20480             // 64 rows
#define OFF_BLO  25600
#define STAGE_SB 30720
#define SMEM_DYN (2 * STAGE_SB)    // 61440 B

__device__ __forceinline__ void cpa16(uint32_t dst, const void* src) {
    asm volatile("cp.async.cg.shared.global [%0], [%1], 16;"
                 :: "r"(dst), "l"(src) : "memory");
}
#define CPA_COMMIT() asm volatile("cp.async.commit_group;" ::: "memory")
#define CPA_WAIT0()  asm volatile("cp.async.wait_group 0;" ::: "memory")

__device__ __forceinline__ void ldm_x4(uint32_t addr, uint32_t& r0, uint32_t& r1,
                                       uint32_t& r2, uint32_t& r3) {
    asm volatile("ldmatrix.sync.aligned.m8n8.x4.shared.b16 {%0,%1,%2,%3}, [%4];"
                 : "=r"(r0), "=r"(r1), "=r"(r2), "=r"(r3) : "r"(addr));
}

__device__ __forceinline__ void mma_f16(float* c, const uint32_t* a, const uint32_t* b) {
    asm volatile(
        "mma.sync.aligned.m16n8k16.row.col.f32.f16.f16.f32 "
        "{%0,%1,%2,%3}, {%4,%5,%6,%7}, {%8,%9}, {%0,%1,%2,%3};"
        : "+f"(c[0]), "+f"(c[1]), "+f"(c[2]), "+f"(c[3])
        : "r"(a[0]), "r"(a[1]), "r"(a[2]), "r"(a[3]), "r"(b[0]), "r"(b[1]));
}

__global__ __launch_bounds__(256, 2)
void gemm1_mma_kernel(const float* __restrict__ x)
{
    extern __shared__ char smem[];
    uint32_t sbase;
    asm("{ .reg .u64 t; cvta.to.shared.u64 t, %1; cvt.u32.u64 %0, t; }"
        : "=r"(sbase) : "l"(smem));

    const int tid   = threadIdx.x;
    const int lane  = tid & 31;
    const int w     = tid >> 5;
    const int mtile = blockIdx.y;     // 0..255
    const int ntile = blockIdx.x;     // 0..15
    const int MW    = (w >> 1) * 32;
    const int NW    = (w & 1) * 32;
    const int m0    = mtile * 128;
    const int n0    = ntile * 64;

    // A (X) load plan: t constant per CTA, b = b0 + row.
    const int tconst = mtile >> 1;
    const int b0     = (mtile & 1) * 128;
    const int r0     = tid >> 3;          // 0..31
    const int c4a    = tid & 7;           // 0..7 (float4 column)
    const float* aptr0 = x + ((size_t)(b0 + r0) * T_ + tconst) * NIN + c4a * 4;
    const size_t ASTRIDE = (size_t)32 * T_ * NIN;   // 32 rows in b
    // STS offsets for A (4 rows per thread, step 32 rows)
    const uint32_t astoff = (uint32_t)(r0 * ROWB + c4a * 8);

    // W cp.async plan: 2 x 16B per thread per chunk (hi, lo)
    const int rw  = tid >> 2;             // 0..63
    const int c4w = tid & 3;              // 0..3
    const char* wsrc_hi = (const char*)(g_whi + (size_t)(n0 + rw) * NINP) + c4w * 16;
    const char* wsrc_lo = (const char*)(g_wlo + (size_t)(n0 + rw) * NINP) + c4w * 16;
    const uint32_t wdoff = (uint32_t)(rw * ROWB + c4w * 16);

    float acc[2][4][4];
#pragma unroll
    for (int mi = 0; mi < 2; mi++)
#pragma unroll
        for (int nj = 0; nj < 4; nj++)
#pragma unroll
            for (int q = 0; q < 4; q++) acc[mi][nj][q] = 0.f;

    // ldmatrix lane addressing
    const int sub = lane >> 3;
    const int l7  = lane & 7;
    const int a_r = MW + (sub & 1) * 8 + l7;
    const int a_c = (sub >> 1) * 8;
    const int b_r = NW + (sub >> 1) * 8 + l7;
    const int b_c = (sub & 1) * 8;

    float4 av[4];

    auto loadX = [&](int c) {
        const int k0 = c * 32;
        const bool ok = (k0 + c4a * 4) < NIN;
#pragma unroll
        for (int i = 0; i < 4; i++)
            av[i] = ok ? *reinterpret_cast<const float4*>(aptr0 + i * ASTRIDE + k0)
                       : make_float4(0.f, 0.f, 0.f, 0.f);
    };
    auto stsX = [&](int stage) {
        char* dst = smem + stage * STAGE_SB;
#pragma unroll
        for (int i = 0; i < 4; i++) {
            uint2 hi, lo;
            split_pack(av[i].x, av[i].y, hi.x, lo.x);
            split_pack(av[i].z, av[i].w, hi.y, lo.y);
            const uint32_t off = astoff + (uint32_t)(i * 32 * ROWB);
            *reinterpret_cast<uint2*>(dst + OFF_AHI + off) = hi;
            *reinterpret_cast<uint2*>(dst + OFF_ALO + off) = lo;
        }
    };
    auto cpaW = [&](int c) {
        const uint32_t sb = sbase + (uint32_t)((c & 1) * STAGE_SB);
        const int o16 = c * 64;           // 32 halfs = 64 B
        cpa16(sb + OFF_BHI + wdoff, wsrc_hi + o16);
        cpa16(sb + OFF_BLO + wdoff, wsrc_lo + o16);
        CPA_COMMIT();
    };

    // ---- prologue ----
    loadX(0);
    stsX(0);
    cpaW(0);
    loadX(1);
    CPA_WAIT0();
    __syncthreads();

    for (int c = 0; c < KCH; c++) {
        if (c + 1 < KCH) cpaW(c + 1);

        // compute chunk c on stage c&1
        const uint32_t stg = sbase + (uint32_t)((c & 1) * STAGE_SB);
#pragma unroll
        for (int mi = 0; mi < 2; mi++) {
            float accT[2][4][4];
#pragma unroll
            for (int g = 0; g < 2; g++)
#pragma unroll
                for (int nj = 0; nj < 4; nj++)
#pragma unroll
                    for (int q = 0; q < 4; q++) accT[g][nj][q] = 0.f;

#pragma unroll
            for (int ks = 0; ks < 2; ks++) {
                uint32_t ah[4], al[4], bh[4][2], bl[4][2];
                const uint32_t ao = stg +
                    (uint32_t)((a_r + mi * 16) * ROWB + (ks * 16 + a_c) * 2);
                ldm_x4(ao + OFF_AHI, ah[0], ah[1], ah[2], ah[3]);
                ldm_x4(ao + OFF_ALO, al[0], al[1], al[2], al[3]);
#pragma unroll
                for (int nt = 0; nt < 2; nt++) {
                    const uint32_t bo = stg +
                        (uint32_t)((b_r + nt * 16) * ROWB + (ks * 16 + b_c) * 2);
                    uint32_t t0, t1, t2, t3;
                    ldm_x4(bo + OFF_BHI, t0, t1, t2, t3);
                    bh[nt * 2][0] = t0; bh[nt * 2][1] = t1;
                    bh[nt * 2 + 1][0] = t2; bh[nt * 2 + 1][1] = t3;
                    ldm_x4(bo + OFF_BLO, t0, t1, t2, t3);
                    bl[nt * 2][0] = t0; bl[nt * 2][1] = t1;
                    bl[nt * 2 + 1][0] = t2; bl[nt * 2 + 1][1] = t3;
                }
#pragma unroll
                for (int nj = 0; nj < 4; nj++) {
                    mma_f16(accT[0][nj], ah, bh[nj]);
                    mma_f16(accT[1][nj], ah, bl[nj]);
                    mma_f16(accT[1][nj], al, bh[nj]);
                }
            }
            // RN drain: acc += hh + c/2048
#pragma unroll
            for (int nj = 0; nj < 4; nj++)
#pragma unroll
                for (int q = 0; q < 4; q++)
                    acc[mi][nj][q] += accT[0][nj][q]
                                    + accT[1][nj][q] * (1.f / 2048.f);
        }

        if (c + 1 < KCH) stsX((c + 1) & 1);
        if (c + 2 < KCH) loadX(c + 2);
        if (c + 1 < KCH) { CPA_WAIT0(); __syncthreads(); }
    }

    // epilogue: undo W scale
    const int mbase = m0 + MW + (lane >> 2);
    const int nbase = n0 + NW + (lane & 3) * 2;
    const float S = 1.f / 1024.f;
#pragma unroll
    for (int mi = 0; mi < 2; mi++)
#pragma unroll
        for (int nj = 0; nj < 4; nj++) {
            const int r = mbase + mi * 16;
            const int col = nbase + nj * 8;
            *reinterpret_cast<float2*>(&g_cur[(size_t)r * NHID + col]) =
                make_float2(acc[mi][nj][0] * S, acc[mi][nj][1] * S);
            *reinterpret_cast<float2*>(&g_cur[(size_t)(r + 8) * NHID + col]) =
                make_float2(acc[mi][nj][2] * S, acc[mi][nj][3] * S);
        }
}

// ---------------------------------------------------------------------------
// Kernel: per-(b,h) LIF scan; t unrolled x4 for MLP; ballot-packed spikes.
// ---------------------------------------------------------------------------
__global__ __launch_bounds__(256)
void spike_scan_kernel()
{
    const int tid  = blockIdx.x * blockDim.x + threadIdx.x;
    const int BH   = B_ * NHID;
    const int widx = tid >> 5;
    float mem1 = 0.f;

#pragma unroll 2
    for (int tb = 0; tb < T_; tb += 4) {
        float cv[4];
#pragma unroll
        for (int u = 0; u < 4; u++)
            cv[u] = g_cur[(size_t)(tb + u) * BH + tid];
#pragma unroll
        for (int u = 0; u < 4; u++) {
            const float reset = (mem1 > THR) ? THR : 0.f;
            mem1 = BETA * mem1 + cv[u] - reset;
            const unsigned bal = __ballot_sync(0xffffffffu, (mem1 - THR) > 0.f);
            if ((tid & 31) == 0)
                g_spk[(size_t)(tb + u) * (BH / 32) + widx] = bal;
        }
    }
}

// ---------------------------------------------------------------------------
// Kernel: Y[t,b,o] = sum_h spk * W2[o,h]
// ---------------------------------------------------------------------------
__global__ __launch_bounds__(256)
void ygemm_kernel(const float* __restrict__ W2)
{
    __shared__ float w2s[NOUT * NHID];
    for (int i = threadIdx.x; i < NOUT * NHID; i += blockDim.x)
        w2s[i] = W2[i];
    __syncthreads();

    const int row = blockIdx.x * blockDim.x + threadIdx.x;
    float acc[NOUT];
#pragma unroll
    for (int o = 0; o < NOUT; o++) acc[o] = 0.f;

    const unsigned* sp = g_spk + (size_t)row * (NHID / 32);
#pragma unroll 4
    for (int wd = 0; wd < NHID / 32; wd++) {
        unsigned bits = sp[wd];
        while (bits) {
            const int j = __ffs(bits) - 1;
            bits &= bits - 1;
            const int h = (wd << 5) + j;
#pragma unroll
            for (int o = 0; o < NOUT; o++)
                acc[o] += w2s[o * NHID + h];
        }
    }

    float* yp = g_y + (size_t)row * NOUT;
#pragma unroll
    for (int o = 0; o < NOUT; o++) yp[o] = acc[o];
}

// ---------------------------------------------------------------------------
// Kernel: mem2 leaky scan, write output [T, B, NOUT]
// ---------------------------------------------------------------------------
__global__ __launch_bounds__(256)
void out_scan_kernel(float* __restrict__ out)
{
    const int idx = blockIdx.x * blockDim.x + threadIdx.x;
    if (idx >= B_ * NOUT) return;
    const int BO = B_ * NOUT;
    float mem2 = 0.f;
#pragma unroll
    for (int tb = 0; tb < T_; tb += 16) {
        float v[16];
#pragma unroll
        for (int u = 0; u < 16; u++)
            v[u] = g_y[(size_t)(tb + u) * BO + idx];
#pragma unroll
        for (int u = 0; u < 16; u++) {
            mem2 = BETA * mem2 + v[u];
            out[(size_t)(tb + u) * BO + idx] = mem2;
        }
    }
}

// ---------------------------------------------------------------------------
extern "C" void kernel_launch(void* const* d_in, const int* in_sizes, int n_in,
                              void* d_out, int out_size)
{
    const float* x  = (const float*)d_in[0];
    const float* W1 = (const float*)d_in[1];
    const float* W2 = (const float*)d_in[2];
    float* out = (float*)d_out;

    cudaFuncSetAttribute(gemm1_mma_kernel,
                         cudaFuncAttributeMaxDynamicSharedMemorySize, SMEM_DYN);

    split_w_kernel<<<(NHID * K4 + 255) / 256, 256>>>(W1);

    dim3 grid1(NHID / 64, M_ / 128);           // (16, 256)
    gemm1_mma_kernel<<<grid1, 256, SMEM_DYN>>>(x);

    spike_scan_kernel<<<(B_ * NHID) / 256, 256>>>();

    ygemm_kernel<<<M_ / 256, 256>>>(W2);

    out_scan_kernel<<<(B_ * NOUT + 255) / 256, 256>>>(out);
}